// round 6
// baseline (speedup 1.0000x reference)
#include <cuda_runtime.h>

#define B_   256
#define T_   128
#define SIG_ 64
#define MET_ 32
#define H_   256
#define F_   16
#define NC   1040   // 4*H + F concatenated gate columns: [i|ste|c|o|fre]
#define NP   1088   // padded to 17*64
#define NB   136    // persistent blocks (<= 148 SMs, guaranteed co-resident)

// ---- persistent scratch (device globals; no allocation) ----
__device__ float g_Wcat[96 * NP];
__device__ float g_Ucat[H_ * NP];
__device__ float g_bcat[NP];
__device__ float g_Xz[(size_t)T_ * B_ * NP];   // precomputed input projections + bias
__device__ float g_Z[2][B_ * NP];              // per-step recurrent GEMM partials
__device__ float g_h[B_ * H_];
__device__ unsigned g_barcnt;

typedef unsigned long long ull;

__device__ __forceinline__ void fma2(ull& d, ull a, ull b) {
    asm("fma.rn.f32x2 %0, %1, %2, %0;" : "+l"(d) : "l"(a), "l"(b));
}
__device__ __forceinline__ void unpk(ull v, float& x, float& y) {
    asm("mov.b64 {%0, %1}, %2;" : "=f"(x), "=f"(y) : "l"(v));
}
__device__ __forceinline__ float hsig(float x) {
    return __saturatef(x * (1.0f / 6.0f) + 0.5f);
}

// Software grid barrier: monotonic counter, pure spin (1 spinner per block).
__device__ __forceinline__ void gbar(unsigned target) {
    __syncthreads();
    if (threadIdx.x == 0) {
        __threadfence();
        atomicAdd(&g_barcnt, 1u);
        unsigned v;
        do {
            asm volatile("ld.volatile.global.u32 %0, [%1];"
                         : "=r"(v) : "l"(&g_barcnt));
        } while (v < target);
        __threadfence();
    }
    __syncthreads();
}

// ---------------------------------------------------------------------------
// Setup: concatenated weights/bias, zero h, zero barrier counter.
// ---------------------------------------------------------------------------
__global__ void setup_kernel(
    const float* __restrict__ Wi_s,  const float* __restrict__ Wste_s,
    const float* __restrict__ Wfre_s,const float* __restrict__ Wc_s,
    const float* __restrict__ Wo_s,
    const float* __restrict__ Wi_m,  const float* __restrict__ Wste_m,
    const float* __restrict__ Wfre_m,const float* __restrict__ Wc_m,
    const float* __restrict__ Wo_m,
    const float* __restrict__ Ui,    const float* __restrict__ Uste,
    const float* __restrict__ Ufre,  const float* __restrict__ Uc,
    const float* __restrict__ Uo,
    const float* __restrict__ bi,    const float* __restrict__ bste,
    const float* __restrict__ bfre,  const float* __restrict__ bc,
    const float* __restrict__ bo)
{
    int tid = blockIdx.x * blockDim.x + threadIdx.x;
    int nth = gridDim.x * blockDim.x;
    if (tid == 0) g_barcnt = 0u;

    for (int idx = tid; idx < 96 * NP; idx += nth) {
        int k = idx / NP, col = idx - k * NP;
        float v = 0.f;
        if (col < 1024) {
            int g = col >> 8, j = col & 255;
            if (k < 64) {
                const float* W = (g == 0) ? Wi_s : (g == 1) ? Wste_s : (g == 2) ? Wc_s : Wo_s;
                v = W[k * H_ + j];
            } else {
                const float* W = (g == 0) ? Wi_m : (g == 1) ? Wste_m : (g == 2) ? Wc_m : Wo_m;
                v = W[(k - 64) * H_ + j];
            }
        } else if (col < NC) {
            int j = col - 1024;
            v = (k < 64) ? Wfre_s[k * F_ + j] : Wfre_m[(k - 64) * F_ + j];
        }
        g_Wcat[idx] = v;
    }

    for (int idx = tid; idx < H_ * NP; idx += nth) {
        int k = idx / NP, col = idx - k * NP;
        float v = 0.f;
        if (col < 1024) {
            int g = col >> 8, j = col & 255;
            const float* U = (g == 0) ? Ui : (g == 1) ? Uste : (g == 2) ? Uc : Uo;
            v = U[k * H_ + j];
        } else if (col < NC) {
            v = Ufre[k * F_ + (col - 1024)];
        }
        g_Ucat[idx] = v;
    }

    for (int col = tid; col < NP; col += nth) {
        float v = 0.f;
        if      (col < 256)  v = bi[col];
        else if (col < 512)  v = bste[col - 256];
        else if (col < 768)  v = bc[col - 512];
        else if (col < 1024) v = bo[col - 768];
        else if (col < NC)   v = bfre[col - 1024];
        g_bcat[col] = v;
    }

    for (int i = tid; i < B_ * H_; i += nth) g_h[i] = 0.f;
}

// ---------------------------------------------------------------------------
// Precompute Xz = [signal|metmast] @ Wcat + bcat.  M=32768, K=96.
// Pack-free f32x2: A duplicated in smem, B read as natural 64-bit pairs.
// Tile 64x64, 256 threads, microtile 4x4, K-chunks of 16, double-buffered.
// ---------------------------------------------------------------------------
__global__ __launch_bounds__(256) void gemm_pre(
    const float* __restrict__ signal, const float* __restrict__ metmast)
{
    __shared__ float2 As2[2][64][16];
    __shared__ __align__(16) float Bs[2][16][64];
    int m0 = blockIdx.x * 64, n0 = blockIdx.y * 64;
    int tid = threadIdx.x;
    int tx = tid & 15, ty4 = (tid >> 4) * 4;
    int nb = tx * 4;

    ull acc[4][2];
    #pragma unroll
    for (int i = 0; i < 4; i++) { acc[i][0] = 0ull; acc[i][1] = 0ull; }

    float asg[4], bsg[4];
    // preload chunk 0 into registers
    #pragma unroll
    for (int l = 0; l < 4; l++) {
        int idx = tid + l * 256;
        int ml = idx >> 4, kl = idx & 15;
        int m = m0 + ml; int bI = m & 255; int tI = m >> 8;
        asg[l] = (kl < SIG_) ? signal[(bI * T_ + tI) * SIG_ + kl]
                             : metmast[(bI * T_ + tI) * MET_ + (kl - SIG_)];
    }
    #pragma unroll
    for (int l = 0; l < 4; l++) {
        int idx = tid + l * 256;
        int kl = idx >> 6, nl = idx & 63;
        bsg[l] = g_Wcat[kl * NP + n0 + nl];
    }
    #pragma unroll
    for (int l = 0; l < 4; l++) {
        int idx = tid + l * 256;
        int ml = idx >> 4, kl = idx & 15;
        As2[0][ml][kl] = make_float2(asg[l], asg[l]);
    }
    #pragma unroll
    for (int l = 0; l < 4; l++) {
        int idx = tid + l * 256;
        int kl = idx >> 6, nl = idx & 63;
        Bs[0][kl][nl] = bsg[l];
    }
    __syncthreads();

    #pragma unroll
    for (int c = 0; c < 6; c++) {
        int p = c & 1;
        if (c < 5) {
            int kk2 = (c + 1) * 16;
            #pragma unroll
            for (int l = 0; l < 4; l++) {
                int idx = tid + l * 256;
                int ml = idx >> 4, kl = idx & 15;
                int k = kk2 + kl;
                int m = m0 + ml; int bI = m & 255; int tI = m >> 8;
                asg[l] = (k < SIG_) ? signal[(bI * T_ + tI) * SIG_ + k]
                                    : metmast[(bI * T_ + tI) * MET_ + (k - SIG_)];
            }
            #pragma unroll
            for (int l = 0; l < 4; l++) {
                int idx = tid + l * 256;
                int kl = idx >> 6, nl = idx & 63;
                bsg[l] = g_Wcat[(kk2 + kl) * NP + n0 + nl];
            }
        }
        #pragma unroll
        for (int k = 0; k < 16; k++) {
            ulonglong2 bb = *(const ulonglong2*)&Bs[p][k][nb];
            #pragma unroll
            for (int i = 0; i < 4; i++) {
                ull a = *(const ull*)&As2[p][ty4 + i][k];
                fma2(acc[i][0], a, bb.x);
                fma2(acc[i][1], a, bb.y);
            }
        }
        if (c < 5) {
            int q = p ^ 1;
            #pragma unroll
            for (int l = 0; l < 4; l++) {
                int idx = tid + l * 256;
                int ml = idx >> 4, kl = idx & 15;
                As2[q][ml][kl] = make_float2(asg[l], asg[l]);
            }
            #pragma unroll
            for (int l = 0; l < 4; l++) {
                int idx = tid + l * 256;
                int kl = idx >> 6, nl = idx & 63;
                Bs[q][kl][nl] = bsg[l];
            }
        }
        __syncthreads();
    }

    #pragma unroll
    for (int i = 0; i < 4; i++) {
        int m = m0 + ty4 + i, n = n0 + nb;
        float4 bias = *(const float4*)&g_bcat[n];
        float x0, x1, x2, x3;
        unpk(acc[i][0], x0, x1); unpk(acc[i][1], x2, x3);
        float4 o = make_float4(x0 + bias.x, x1 + bias.y, x2 + bias.z, x3 + bias.w);
        *(float4*)&g_Xz[(size_t)m * NP + n] = o;
    }
}

// ---------------------------------------------------------------------------
// Persistent kernel: all 128 time steps.  S-state in registers.
// GEMM: tile 64x64 (K=128 per block via ks split), 512 threads split as
// 2 column-halves of 256; microtile 2m x 4n; pack-free f32x2; double-buffered.
// Final projection fused at t=T.
// ---------------------------------------------------------------------------
__global__ __launch_bounds__(512, 1) void persist(
    const float* __restrict__ Ua, const float* __restrict__ ba,
    const float* __restrict__ Wp, const float* __restrict__ bp,
    const float* __restrict__ fcw, const float* __restrict__ fcb,
    float* __restrict__ out)
{
    __shared__ float2 As2[2][64][16];
    __shared__ __align__(16) float Bs[2][16][64];
    __shared__ float fre_sh[2][16];
    __shared__ float csh[16], ssh[16], ua_sh[16];
    __shared__ float warp_sums[16];

    int tid = threadIdx.x;
    int blk = blockIdx.x;
    // GEMM tile assignment: 4 m-tiles x 17 n-tiles x 2 k-splits = 136
    int r = blk % 68, ks = blk / 68;
    int m0 = (r & 3) * 64, n0 = (r >> 2) * 64;
    int kbase = ks * 128;
    // thread micro-mapping: column half kh, 8 n-groups x 32 m-groups
    int kh = tid >> 8;
    int txg = tid & 7, tyg = (tid >> 3) & 31;
    int ty2 = tyg * 2;
    int nb = kh * 32 + txg * 4;

    int gid = blk * 512 + tid;
    int b = gid >> 8, h = gid & 255;
    bool has_state = (blk < 128);

    float Sre[16], Sim[16];
    #pragma unroll
    for (int f = 0; f < 16; f++) { Sre[f] = 0.f; Sim[f] = 0.f; }

    float bah = 0.f, wph = 0.f;
    if (has_state) { bah = ba[h]; wph = Wp[h]; }
    if (tid < 16) ua_sh[tid] = Ua[tid];

    unsigned epoch = 0;

    for (int t = 1; t <= T_; t++) {
        // ---- prefetch update inputs (depend only on t, not on barrier) ----
        const float* xrow = g_Xz + ((size_t)(t - 1) * B_ + b) * NP;
        float pf0 = 0.f, pf1 = 0.f, pf2 = 0.f, pf3 = 0.f, pf_zf = 0.f;
        if (has_state) {
            pf0 = __ldcs(&xrow[h]);
            pf1 = __ldcs(&xrow[256 + h]);
            pf2 = __ldcs(&xrow[512 + h]);
            pf3 = __ldcs(&xrow[768 + h]);
            if (tid < 32) {
                int f = tid & 15, bb2 = tid >> 4;
                pf_zf = __ldcs(&g_Xz[((size_t)(t - 1) * B_ + blk * 2 + bb2) * NP + 1024 + f]);
            }
            if (tid < 16) {
                int p = (t * tid) & 15;
                csh[tid] = cospif((float)p * 0.125f);
                ssh[tid] = sinpif((float)p * 0.125f);
            }
        }

        if (t > 1) {
            // ---- GEMM phase: Z[ks] = h @ Ucat[kbase:kbase+128, :] ----
            ull acc00 = 0, acc01 = 0, acc10 = 0, acc11 = 0;
            // preload chunk 0
            {
                float asg[2], bsg[2];
                #pragma unroll
                for (int l = 0; l < 2; l++) {
                    int idx = tid + l * 512;
                    int ml = idx >> 4, kl = idx & 15;
                    asg[l] = __ldcg(&g_h[(m0 + ml) * H_ + kbase + kl]);
                }
                #pragma unroll
                for (int l = 0; l < 2; l++) {
                    int idx = tid + l * 512;
                    int kl = idx >> 6, nl = idx & 63;
                    bsg[l] = g_Ucat[(kbase + kl) * NP + n0 + nl];
                }
                #pragma unroll
                for (int l = 0; l < 2; l++) {
                    int idx = tid + l * 512;
                    int ml = idx >> 4, kl = idx & 15;
                    As2[0][ml][kl] = make_float2(asg[l], asg[l]);
                }
                #pragma unroll
                for (int l = 0; l < 2; l++) {
                    int idx = tid + l * 512;
                    int kl = idx >> 6, nl = idx & 63;
                    Bs[0][kl][nl] = bsg[l];
                }
            }
            __syncthreads();

            #pragma unroll
            for (int c = 0; c < 8; c++) {
                int p = c & 1;
                float asg[2], bsg[2];
                if (c < 7) {
                    int kk2 = (c + 1) * 16;
                    #pragma unroll
                    for (int l = 0; l < 2; l++) {
                        int idx = tid + l * 512;
                        int ml = idx >> 4, kl = idx & 15;
                        asg[l] = __ldcg(&g_h[(m0 + ml) * H_ + kbase + kk2 + kl]);
                    }
                    #pragma unroll
                    for (int l = 0; l < 2; l++) {
                        int idx = tid + l * 512;
                        int kl = idx >> 6, nl = idx & 63;
                        bsg[l] = g_Ucat[(kbase + kk2 + kl) * NP + n0 + nl];
                    }
                }
                #pragma unroll
                for (int k = 0; k < 16; k++) {
                    ull a0 = *(const ull*)&As2[p][ty2][k];
                    ull a1 = *(const ull*)&As2[p][ty2 + 1][k];
                    ulonglong2 bb = *(const ulonglong2*)&Bs[p][k][nb];
                    fma2(acc00, a0, bb.x); fma2(acc01, a0, bb.y);
                    fma2(acc10, a1, bb.x); fma2(acc11, a1, bb.y);
                }
                if (c < 7) {
                    int q = p ^ 1;
                    #pragma unroll
                    for (int l = 0; l < 2; l++) {
                        int idx = tid + l * 512;
                        int ml = idx >> 4, kl = idx & 15;
                        As2[q][ml][kl] = make_float2(asg[l], asg[l]);
                    }
                    #pragma unroll
                    for (int l = 0; l < 2; l++) {
                        int idx = tid + l * 512;
                        int kl = idx >> 6, nl = idx & 63;
                        Bs[q][kl][nl] = bsg[l];
                    }
                }
                __syncthreads();
            }
            {
                int m = m0 + ty2, n = n0 + nb;
                float x0, x1, x2, x3;
                unpk(acc00, x0, x1); unpk(acc01, x2, x3);
                __stcg((float4*)&g_Z[ks][m * NP + n], make_float4(x0, x1, x2, x3));
                unpk(acc10, x0, x1); unpk(acc11, x2, x3);
                __stcg((float4*)&g_Z[ks][(m + 1) * NP + n], make_float4(x0, x1, x2, x3));
            }
            epoch += NB; gbar(epoch);
        }

        // ---- update phase ----
        if (has_state) {
            const float* z0 = g_Z[0] + b * NP;
            const float* z1 = g_Z[1] + b * NP;

            if (tid < 32) {
                int f = tid & 15, bb2 = tid >> 4;
                float zf = pf_zf;
                if (t > 1) {
                    int bloc = blk * 2 + bb2;
                    zf += __ldcg(&g_Z[0][bloc * NP + 1024 + f])
                        + __ldcg(&g_Z[1][bloc * NP + 1024 + f]);
                }
                fre_sh[bb2][f] = hsig(zf);
            }
            __syncthreads();

            float zi = pf0, zs = pf1, zc = pf2, zo = pf3;
            if (t > 1) {
                zi += __ldcg(&z0[h])       + __ldcg(&z1[h]);
                zs += __ldcg(&z0[256 + h]) + __ldcg(&z1[256 + h]);
                zc += __ldcg(&z0[512 + h]) + __ldcg(&z1[512 + h]);
                zo += __ldcg(&z0[768 + h]) + __ldcg(&z1[768 + h]);
            }
            float ig  = hsig(zi);
            float ste = hsig(zs);
            float og  = hsig(zo);
            float cg  = ig * tanhf(zc);

            int bb2 = tid >> 8;
            float acc = 0.f;
            #pragma unroll
            for (int f = 0; f < 16; f++) {
                float ff = ste * fre_sh[bb2][f];
                float Sr = ff * Sre[f] + cg * csh[f];
                float Si = ff * Sim[f] + cg * ssh[f];
                Sre[f] = Sr; Sim[f] = Si;
                acc += (Sr * Sr + Si * Si) * ua_sh[f];
            }
            float hn = og * tanhf(acc + bah);
            if (t < T_) {
                __stcg(&g_h[b * H_ + h], hn);
            } else {
                // fused final projection: out[b] = (h·Wp + bp)*fcw + fcb
                float v = hn * wph;
                #pragma unroll
                for (int o = 16; o; o >>= 1) v += __shfl_down_sync(0xffffffffu, v, o);
                if ((tid & 31) == 0) warp_sums[tid >> 5] = v;
                __syncthreads();
                if (tid < 2) {
                    float s = 0.f;
                    #pragma unroll
                    for (int w = 0; w < 8; w++) s += warp_sums[tid * 8 + w];
                    out[blk * 2 + tid] = (s + bp[0]) * fcw[0] + fcb[0];
                }
            }
        }
        if (t < T_) { epoch += NB; gbar(epoch); }
    }
}

// ---------------------------------------------------------------------------
extern "C" void kernel_launch(void* const* d_in, const int* in_sizes, int n_in,
                              void* d_out, int out_size)
{
    (void)in_sizes; (void)n_in; (void)out_size;
    const float* signal  = (const float*)d_in[0];
    const float* metmast = (const float*)d_in[1];
    const float* Wi_s    = (const float*)d_in[2];
    const float* Wste_s  = (const float*)d_in[3];
    const float* Wfre_s  = (const float*)d_in[4];
    const float* Wc_s    = (const float*)d_in[5];
    const float* Wo_s    = (const float*)d_in[6];
    const float* Wi_m    = (const float*)d_in[7];
    const float* Wste_m  = (const float*)d_in[8];
    const float* Wfre_m  = (const float*)d_in[9];
    const float* Wc_m    = (const float*)d_in[10];
    const float* Wo_m    = (const float*)d_in[11];
    const float* Ui      = (const float*)d_in[12];
    const float* bi      = (const float*)d_in[13];
    const float* Uste    = (const float*)d_in[14];
    const float* bste    = (const float*)d_in[15];
    const float* Ufre    = (const float*)d_in[16];
    const float* bfre    = (const float*)d_in[17];
    const float* Uc      = (const float*)d_in[18];
    const float* bc      = (const float*)d_in[19];
    const float* Uo      = (const float*)d_in[20];
    const float* bo      = (const float*)d_in[21];
    const float* Ua      = (const float*)d_in[22];
    const float* ba      = (const float*)d_in[23];
    const float* Wp      = (const float*)d_in[24];
    const float* bp      = (const float*)d_in[25];
    const float* fcw     = (const float*)d_in[26];
    const float* fcb     = (const float*)d_in[27];
    float* out = (float*)d_out;

    setup_kernel<<<512, 256>>>(Wi_s, Wste_s, Wfre_s, Wc_s, Wo_s,
                               Wi_m, Wste_m, Wfre_m, Wc_m, Wo_m,
                               Ui, Uste, Ufre, Uc, Uo,
                               bi, bste, bfre, bc, bo);

    gemm_pre<<<dim3(T_ * B_ / 64, NP / 64), 256>>>(signal, metmast);

    persist<<<NB, 512>>>(Ua, ba, Wp, bp, fcw, fcb, out);
}

// round 7
// speedup vs baseline: 1.0689x; 1.0689x over previous
#include <cuda_runtime.h>

#define B_   256
#define T_   128
#define SIG_ 64
#define MET_ 32
#define H_   256
#define F_   16
#define NPRE 1280      // pre-GEMM N: 16 chunks x 80 cols [i16|ste16|c16|o16|fre16]
#define C_   16        // blocks per group
#define G_   8         // groups
#define NBLK 128
#define USTRIDE 88     // U_s row stride (floats), 352B: 16B-aligned rows
#define HSTRIDE 258    // h_dup row stride (float2)
#define ZSTRIDE 84

typedef unsigned long long ull;

// ---- persistent scratch (device globals; no allocation) ----
__device__ float g_Wcat[96 * NPRE];
__device__ float g_bcat[NPRE];
__device__ float g_Ucat[C_ * 256 * 80];            // [chunk][k][80]
__device__ float g_Xz[(size_t)B_ * T_ * NPRE];     // [b][t][1280]
__device__ float g_h[B_ * H_];
__device__ unsigned g_bar[G_ * 32];                // per-group counters, 128B apart

__device__ __forceinline__ void fma2(ull& d, ull a, ull b) {
    asm("fma.rn.f32x2 %0, %1, %2, %0;" : "+l"(d) : "l"(a), "l"(b));
}
__device__ __forceinline__ float2 ull2f2(ull v) {
    float2 r; asm("mov.b64 {%0,%1}, %2;" : "=f"(r.x), "=f"(r.y) : "l"(v)); return r;
}
__device__ __forceinline__ float hsig(float x) {
    return __saturatef(x * (1.0f / 6.0f) + 0.5f);
}

// ---------------------------------------------------------------------------
// Setup: permuted concatenated weights/bias, zero h and barrier counters.
// Column layout, chunk c (c=0..15), pos 0..79:
//   pos<64: gate g=pos>>4 (i,ste,c,o), unit u = c*16 + (pos&15)
//   pos>=64: fre f = pos-64
// ---------------------------------------------------------------------------
__global__ void setup_kernel(
    const float* __restrict__ Wi_s,  const float* __restrict__ Wste_s,
    const float* __restrict__ Wfre_s,const float* __restrict__ Wc_s,
    const float* __restrict__ Wo_s,
    const float* __restrict__ Wi_m,  const float* __restrict__ Wste_m,
    const float* __restrict__ Wfre_m,const float* __restrict__ Wc_m,
    const float* __restrict__ Wo_m,
    const float* __restrict__ Ui,    const float* __restrict__ Uste,
    const float* __restrict__ Ufre,  const float* __restrict__ Uc,
    const float* __restrict__ Uo,
    const float* __restrict__ bi,    const float* __restrict__ bste,
    const float* __restrict__ bfre,  const float* __restrict__ bc,
    const float* __restrict__ bo)
{
    int tid = blockIdx.x * blockDim.x + threadIdx.x;
    int nth = gridDim.x * blockDim.x;

    // Wcat [96][1280]
    for (int idx = tid; idx < 96 * NPRE; idx += nth) {
        int k = idx / NPRE, n = idx - k * NPRE;
        int chunk = n / 80, pos = n - chunk * 80;
        float v;
        if (pos < 64) {
            int gg = pos >> 4, u = chunk * 16 + (pos & 15);
            if (k < 64) {
                const float* W = (gg == 0) ? Wi_s : (gg == 1) ? Wste_s : (gg == 2) ? Wc_s : Wo_s;
                v = W[k * H_ + u];
            } else {
                const float* W = (gg == 0) ? Wi_m : (gg == 1) ? Wste_m : (gg == 2) ? Wc_m : Wo_m;
                v = W[(k - 64) * H_ + u];
            }
        } else {
            int f = pos - 64;
            v = (k < 64) ? Wfre_s[k * F_ + f] : Wfre_m[(k - 64) * F_ + f];
        }
        g_Wcat[idx] = v;
    }

    // bcat [1280]
    for (int n = tid; n < NPRE; n += nth) {
        int chunk = n / 80, pos = n - chunk * 80;
        float v;
        if (pos < 64) {
            int gg = pos >> 4, u = chunk * 16 + (pos & 15);
            v = (gg == 0) ? bi[u] : (gg == 1) ? bste[u] : (gg == 2) ? bc[u] : bo[u];
        } else {
            v = bfre[pos - 64];
        }
        g_bcat[n] = v;
    }

    // Ucat [16][256][80]
    for (int idx = tid; idx < C_ * 256 * 80; idx += nth) {
        int chunk = idx / (256 * 80);
        int rem = idx - chunk * (256 * 80);
        int k = rem / 80, pos = rem - k * 80;
        float v;
        if (pos < 64) {
            int gg = pos >> 4, u = chunk * 16 + (pos & 15);
            const float* U = (gg == 0) ? Ui : (gg == 1) ? Uste : (gg == 2) ? Uc : Uo;
            v = U[k * H_ + u];
        } else {
            v = Ufre[k * F_ + (pos - 64)];
        }
        g_Ucat[idx] = v;
    }

    for (int i = tid; i < B_ * H_; i += nth) g_h[i] = 0.f;
    for (int i = tid; i < G_ * 32; i += nth) g_bar[i] = 0u;
}

// ---------------------------------------------------------------------------
// Precompute Xz = [signal|metmast] @ Wcat + bcat.  M=32768 (m=b*T+t), K=96.
// Fully coalesced A loads (m consecutive = t consecutive within a batch row).
// ---------------------------------------------------------------------------
__global__ __launch_bounds__(256) void gemm_pre(
    const float* __restrict__ signal, const float* __restrict__ metmast)
{
    __shared__ float2 As2[2][64][16];
    __shared__ __align__(16) float Bs[2][16][64];
    int m0 = blockIdx.x * 64, n0 = blockIdx.y * 64;
    int tid = threadIdx.x;
    int tx = tid & 15, ty4 = (tid >> 4) * 4;
    int nb = tx * 4;

    ull acc[4][2];
    #pragma unroll
    for (int i = 0; i < 4; i++) { acc[i][0] = 0ull; acc[i][1] = 0ull; }

    float asg[4], bsg[4];
    #pragma unroll
    for (int l = 0; l < 4; l++) {
        int idx = tid + l * 256;
        int ml = idx >> 4, kl = idx & 15;
        int m = m0 + ml;
        asg[l] = (kl < SIG_) ? signal[(size_t)m * SIG_ + kl]
                             : metmast[(size_t)m * MET_ + (kl - SIG_)];
    }
    #pragma unroll
    for (int l = 0; l < 4; l++) {
        int idx = tid + l * 256;
        int kl = idx >> 6, nl = idx & 63;
        bsg[l] = g_Wcat[kl * NPRE + n0 + nl];
    }
    #pragma unroll
    for (int l = 0; l < 4; l++) {
        int idx = tid + l * 256;
        int ml = idx >> 4, kl = idx & 15;
        As2[0][ml][kl] = make_float2(asg[l], asg[l]);
    }
    #pragma unroll
    for (int l = 0; l < 4; l++) {
        int idx = tid + l * 256;
        int kl = idx >> 6, nl = idx & 63;
        Bs[0][kl][nl] = bsg[l];
    }
    __syncthreads();

    #pragma unroll
    for (int c = 0; c < 6; c++) {
        int p = c & 1;
        if (c < 5) {
            int kk2 = (c + 1) * 16;
            #pragma unroll
            for (int l = 0; l < 4; l++) {
                int idx = tid + l * 256;
                int ml = idx >> 4, kl = idx & 15;
                int k = kk2 + kl;
                int m = m0 + ml;
                asg[l] = (k < SIG_) ? signal[(size_t)m * SIG_ + k]
                                    : metmast[(size_t)m * MET_ + (k - SIG_)];
            }
            #pragma unroll
            for (int l = 0; l < 4; l++) {
                int idx = tid + l * 256;
                int kl = idx >> 6, nl = idx & 63;
                bsg[l] = g_Wcat[(kk2 + kl) * NPRE + n0 + nl];
            }
        }
        #pragma unroll
        for (int k = 0; k < 16; k++) {
            ulonglong2 bb = *(const ulonglong2*)&Bs[p][k][nb];
            #pragma unroll
            for (int i = 0; i < 4; i++) {
                ull a = *(const ull*)&As2[p][ty4 + i][k];
                fma2(acc[i][0], a, bb.x);
                fma2(acc[i][1], a, bb.y);
            }
        }
        if (c < 5) {
            int q = p ^ 1;
            #pragma unroll
            for (int l = 0; l < 4; l++) {
                int idx = tid + l * 256;
                int ml = idx >> 4, kl = idx & 15;
                As2[q][ml][kl] = make_float2(asg[l], asg[l]);
            }
            #pragma unroll
            for (int l = 0; l < 4; l++) {
                int idx = tid + l * 256;
                int kl = idx >> 6, nl = idx & 63;
                Bs[q][kl][nl] = bsg[l];
            }
        }
        __syncthreads();
    }

    #pragma unroll
    for (int i = 0; i < 4; i++) {
        int m = m0 + ty4 + i, n = n0 + nb;
        float4 bias = *(const float4*)&g_bcat[n];
        float2 x01 = ull2f2(acc[i][0]), x23 = ull2f2(acc[i][1]);
        float4 o = make_float4(x01.x + bias.x, x01.y + bias.y,
                               x23.x + bias.z, x23.y + bias.w);
        *(float4*)&g_Xz[(size_t)m * NPRE + n] = o;
    }
}

// ---------------------------------------------------------------------------
// Persistent kernel: 128 blocks = 8 groups x 16 blocks.  Group owns 32 batch
// rows; block c owns units c*16..c*16+15.  U-slice + h live in smem; Z is
// block-local smem.  One group barrier per step (h exchange only).
// ---------------------------------------------------------------------------
extern __shared__ __align__(16) char smraw[];

__global__ void __launch_bounds__(512, 1) persist(
    const float* __restrict__ Ua, const float* __restrict__ ba,
    const float* __restrict__ Wp, const float* __restrict__ bp,
    const float* __restrict__ fcw, const float* __restrict__ fcb,
    float* __restrict__ out)
{
    float*  U_s   = (float*)(smraw);                    // [256][USTRIDE]   90112 B
    float2* h_dup = (float2*)(smraw + 90112);           // [32][HSTRIDE]    66048 B
    float*  Z_sm  = (float*)(smraw + 156160);           // [32][ZSTRIDE]    10752 B
    float2* red4  = (float2*)(smraw + 166912);          // [256][4]          8192 B
    float2* redf  = (float2*)(smraw + 175104);          // [256]             2048 B
    float*  fre_sm= (float*)(smraw + 177152);           // [32][16]          2048 B
    __shared__ float csh[16], ssh[16], ua_sh[16];

    int tid = threadIdx.x;
    int blk = blockIdx.x;
    int g = blk >> 4, c = blk & 15;
    int gb0 = g * 32;

    // update mapping: thread = (row, unit-local)
    int row_u = tid >> 4, ul = tid & 15;
    int b_u = gb0 + row_u;
    int u_glob = c * 16 + ul;
    // main GEMM mapping
    int cg = tid & 15, rg = (tid >> 4) & 15, kh = tid >> 8;
    // fre GEMM mapping
    int fcp = tid & 7, fr = (tid >> 3) & 31;

    // load U slice into smem (once)
    for (int i = tid; i < 256 * 80; i += 512) {
        int k = i / 80, p = i - k * 80;
        U_s[k * USTRIDE + p] = g_Ucat[(c * 256 + k) * 80 + p];
    }
    if (tid < 16) ua_sh[tid] = Ua[tid];
    float bah = ba[u_glob];

    float Sre[16], Sim[16];
    #pragma unroll
    for (int f = 0; f < 16; f++) { Sre[f] = 0.f; Sim[f] = 0.f; }
    __syncthreads();

    unsigned epoch = 0;
    unsigned* barp = &g_bar[g * 32];

    for (int t = 1; t <= T_; t++) {
        // ---- prefetch gate inputs for this step (coalesced, streaming) ----
        size_t xi = ((size_t)b_u * T_ + (t - 1)) * NPRE + c * 80 + ul;
        float pzi = __ldcs(&g_Xz[xi]);
        float pzs = __ldcs(&g_Xz[xi + 16]);
        float pzc = __ldcs(&g_Xz[xi + 32]);
        float pzo = __ldcs(&g_Xz[xi + 48]);
        float pzf = __ldcs(&g_Xz[xi + 64 - ul + ul]);  // fre col = base+64+f, f=ul
        pzf = __ldcs(&g_Xz[((size_t)b_u * T_ + (t - 1)) * NPRE + c * 80 + 64 + ul]);
        if (tid < 16) {
            int p = (t * tid) & 15;
            csh[tid] = cospif((float)p * 0.125f);
            ssh[tid] = sinpif((float)p * 0.125f);
        }

        if (t > 1) {
            // ---- main GEMM: Z[32 x 64 gate cols] = h @ U_s, k split in 2 ----
            ull a00 = 0, a01 = 0, a10 = 0, a11 = 0;
            {
                const float2* hp0 = h_dup + (rg * 2) * HSTRIDE + kh * 128;
                const float2* hp1 = hp0 + HSTRIDE;
                const float* up = U_s + (kh * 128) * USTRIDE + cg * 4;
                #pragma unroll 4
                for (int k = 0; k < 128; k++) {
                    ull h0 = *(const ull*)(hp0 + k);
                    ull h1 = *(const ull*)(hp1 + k);
                    ulonglong2 uu = *(const ulonglong2*)(up + k * USTRIDE);
                    fma2(a00, h0, uu.x); fma2(a01, h0, uu.y);
                    fma2(a10, h1, uu.x); fma2(a11, h1, uu.y);
                }
            }
            // ---- fre GEMM: Z[32 x 16 fre cols] ----
            ull af = 0;
            {
                const float2* hp = h_dup + fr * HSTRIDE + kh * 128;
                const float* up = U_s + (kh * 128) * USTRIDE + 64 + fcp * 2;
                #pragma unroll 4
                for (int k = 0; k < 128; k++) {
                    ull hh = *(const ull*)(hp + k);
                    ull uu = *(const ull*)(up + k * USTRIDE);
                    fma2(af, hh, uu);
                }
            }
            // ---- k-split reduction + write Z_sm ----
            int p = tid & 255;
            if (kh == 1) {
                red4[p * 4 + 0] = ull2f2(a00);
                red4[p * 4 + 1] = ull2f2(a01);
                red4[p * 4 + 2] = ull2f2(a10);
                red4[p * 4 + 3] = ull2f2(a11);
                redf[p] = ull2f2(af);
            }
            __syncthreads();
            if (kh == 0) {
                float2 m00 = ull2f2(a00), m01 = ull2f2(a01);
                float2 m10 = ull2f2(a10), m11 = ull2f2(a11);
                float2 q0 = red4[p * 4 + 0], q1 = red4[p * 4 + 1];
                float2 q2 = red4[p * 4 + 2], q3 = red4[p * 4 + 3];
                int r0 = rg * 2, col = cg * 4;
                *(float2*)&Z_sm[r0 * ZSTRIDE + col] =
                    make_float2(m00.x + q0.x, m00.y + q0.y);
                *(float2*)&Z_sm[r0 * ZSTRIDE + col + 2] =
                    make_float2(m01.x + q1.x, m01.y + q1.y);
                *(float2*)&Z_sm[(r0 + 1) * ZSTRIDE + col] =
                    make_float2(m10.x + q2.x, m10.y + q2.y);
                *(float2*)&Z_sm[(r0 + 1) * ZSTRIDE + col + 2] =
                    make_float2(m11.x + q3.x, m11.y + q3.y);
                float2 mf = ull2f2(af), qf = redf[p];
                *(float2*)&Z_sm[fr * ZSTRIDE + 64 + fcp * 2] =
                    make_float2(mf.x + qf.x, mf.y + qf.y);
            }
            __syncthreads();
        }

        // ---- fre gate ----
        {
            float zf = pzf;
            if (t > 1) zf += Z_sm[row_u * ZSTRIDE + 64 + ul];
            fre_sm[row_u * 16 + ul] = hsig(zf);
        }
        __syncthreads();

        // ---- gates + SFM state update ----
        float zi = pzi, zs = pzs, zc = pzc, zo = pzo;
        if (t > 1) {
            zi += Z_sm[row_u * ZSTRIDE + ul];
            zs += Z_sm[row_u * ZSTRIDE + 16 + ul];
            zc += Z_sm[row_u * ZSTRIDE + 32 + ul];
            zo += Z_sm[row_u * ZSTRIDE + 48 + ul];
        }
        float ig  = hsig(zi);
        float ste = hsig(zs);
        float og  = hsig(zo);
        float cgt = ig * tanhf(zc);

        float acc = 0.f;
        #pragma unroll
        for (int f = 0; f < 16; f++) {
            float ff = ste * fre_sm[row_u * 16 + f];
            float Sr = ff * Sre[f] + cgt * csh[f];
            float Si = ff * Sim[f] + cgt * ssh[f];
            Sre[f] = Sr; Sim[f] = Si;
            acc += (Sr * Sr + Si * Si) * ua_sh[f];
        }
        float hn = og * tanhf(acc + bah);
        g_h[b_u * H_ + u_glob] = hn;

        // ---- group barrier (h exchange) ----
        epoch += C_;
        __syncthreads();
        if (tid == 0) {
            __threadfence();
            atomicAdd(barp, 1u);
            unsigned v;
            do {
                asm volatile("ld.volatile.global.u32 %0, [%1];"
                             : "=r"(v) : "l"(barp));
            } while (v < epoch);
            __threadfence();
        }
        __syncthreads();

        // ---- reload group h into smem (duplicated) for next step ----
        if (t < T_) {
            for (int i = tid; i < 32 * 256; i += 512) {
                int r = i >> 8, k = i & 255;
                float v = __ldcg(&g_h[(gb0 + r) * H_ + k]);
                h_dup[r * HSTRIDE + k] = make_float2(v, v);
            }
            __syncthreads();
        }
    }

    // ---- final projection: block c==0 of each group handles its 32 rows ----
    if (c == 0) {
        int row = tid >> 4, j = tid & 15;
        float s = 0.f;
        #pragma unroll
        for (int l = 0; l < 16; l++)
            s += __ldcg(&g_h[(gb0 + row) * H_ + j * 16 + l]) * Wp[j * 16 + l];
        #pragma unroll
        for (int o = 8; o; o >>= 1) s += __shfl_xor_sync(0xffffffffu, s, o);
        if (j == 0) out[gb0 + row] = (s + bp[0]) * fcw[0] + fcb[0];
    }
}

// ---------------------------------------------------------------------------
#define SMEM_PERSIST 179200

extern "C" void kernel_launch(void* const* d_in, const int* in_sizes, int n_in,
                              void* d_out, int out_size)
{
    (void)in_sizes; (void)n_in; (void)out_size;
    const float* signal  = (const float*)d_in[0];
    const float* metmast = (const float*)d_in[1];
    const float* Wi_s    = (const float*)d_in[2];
    const float* Wste_s  = (const float*)d_in[3];
    const float* Wfre_s  = (const float*)d_in[4];
    const float* Wc_s    = (const float*)d_in[5];
    const float* Wo_s    = (const float*)d_in[6];
    const float* Wi_m    = (const float*)d_in[7];
    const float* Wste_m  = (const float*)d_in[8];
    const float* Wfre_m  = (const float*)d_in[9];
    const float* Wc_m    = (const float*)d_in[10];
    const float* Wo_m    = (const float*)d_in[11];
    const float* Ui      = (const float*)d_in[12];
    const float* bi      = (const float*)d_in[13];
    const float* Uste    = (const float*)d_in[14];
    const float* bste    = (const float*)d_in[15];
    const float* Ufre    = (const float*)d_in[16];
    const float* bfre    = (const float*)d_in[17];
    const float* Uc      = (const float*)d_in[18];
    const float* bc      = (const float*)d_in[19];
    const float* Uo      = (const float*)d_in[20];
    const float* bo      = (const float*)d_in[21];
    const float* Ua      = (const float*)d_in[22];
    const float* ba      = (const float*)d_in[23];
    const float* Wp      = (const float*)d_in[24];
    const float* bp      = (const float*)d_in[25];
    const float* fcw     = (const float*)d_in[26];
    const float* fcb     = (const float*)d_in[27];
    float* out = (float*)d_out;

    cudaFuncSetAttribute(persist,
                         cudaFuncAttributeMaxDynamicSharedMemorySize,
                         SMEM_PERSIST);

    setup_kernel<<<512, 256>>>(Wi_s, Wste_s, Wfre_s, Wc_s, Wo_s,
                               Wi_m, Wste_m, Wfre_m, Wc_m, Wo_m,
                               Ui, Uste, Ufre, Uc, Uo,
                               bi, bste, bfre, bc, bo);

    gemm_pre<<<dim3(B_ * T_ / 64, NPRE / 64), 256>>>(signal, metmast);

    persist<<<NBLK, 512, SMEM_PERSIST>>>(Ua, ba, Wp, bp, fcw, fcb, out);
}

// round 10
// speedup vs baseline: 1.0691x; 1.0002x over previous
#include <cuda_runtime.h>

#define B_   256
#define T_   128
#define SIG_ 64
#define MET_ 32
#define H_   256
#define F_   16
#define NPRE 1280      // pre-GEMM N: 16 chunks x 80 cols [i16|ste16|c16|o16|fre16]
#define C_   16        // blocks per group
#define G_   8         // groups
#define NBLK 128
#define USTRIDE 88     // U_s row stride (floats), 352B: 16B-aligned rows
#define HSTRIDE 258    // h_dup row stride (float2)
#define ZSTRIDE 84

typedef unsigned long long ull;

// ---- persistent scratch (device globals; no allocation) ----
__device__ float g_Wcat[96 * NPRE];
__device__ float g_bcat[NPRE];
__device__ float g_Ucat[C_ * 256 * 80];            // [chunk][k][80]
__device__ float g_Xz[(size_t)B_ * T_ * NPRE];     // [b][t][1280]
__device__ float g_h[B_ * H_];
__device__ unsigned g_bar[G_ * 32];                // per-group counters, 128B apart

__device__ __forceinline__ void fma2(ull& d, ull a, ull b) {
    asm("fma.rn.f32x2 %0, %1, %2, %0;" : "+l"(d) : "l"(a), "l"(b));
}
__device__ __forceinline__ float2 ull2f2(ull v) {
    float2 r; asm("mov.b64 {%0,%1}, %2;" : "=f"(r.x), "=f"(r.y) : "l"(v)); return r;
}
__device__ __forceinline__ float hsig(float x) {
    return __saturatef(x * (1.0f / 6.0f) + 0.5f);
}

// ---------------------------------------------------------------------------
// Setup: permuted concatenated weights/bias, zero h and barrier counters.
// Column layout, chunk c (c=0..15), pos 0..79:
//   pos<64: gate g=pos>>4 (i,ste,c,o), unit u = c*16 + (pos&15)
//   pos>=64: fre f = pos-64
// ---------------------------------------------------------------------------
__global__ void setup_kernel(
    const float* __restrict__ Wi_s,  const float* __restrict__ Wste_s,
    const float* __restrict__ Wfre_s,const float* __restrict__ Wc_s,
    const float* __restrict__ Wo_s,
    const float* __restrict__ Wi_m,  const float* __restrict__ Wste_m,
    const float* __restrict__ Wfre_m,const float* __restrict__ Wc_m,
    const float* __restrict__ Wo_m,
    const float* __restrict__ Ui,    const float* __restrict__ Uste,
    const float* __restrict__ Ufre,  const float* __restrict__ Uc,
    const float* __restrict__ Uo,
    const float* __restrict__ bi,    const float* __restrict__ bste,
    const float* __restrict__ bfre,  const float* __restrict__ bc,
    const float* __restrict__ bo)
{
    int tid = blockIdx.x * blockDim.x + threadIdx.x;
    int nth = gridDim.x * blockDim.x;

    // Wcat [96][1280]
    for (int idx = tid; idx < 96 * NPRE; idx += nth) {
        int k = idx / NPRE, n = idx - k * NPRE;
        int chunk = n / 80, pos = n - chunk * 80;
        float v;
        if (pos < 64) {
            int gg = pos >> 4, u = chunk * 16 + (pos & 15);
            if (k < 64) {
                const float* W = (gg == 0) ? Wi_s : (gg == 1) ? Wste_s : (gg == 2) ? Wc_s : Wo_s;
                v = W[k * H_ + u];
            } else {
                const float* W = (gg == 0) ? Wi_m : (gg == 1) ? Wste_m : (gg == 2) ? Wc_m : Wo_m;
                v = W[(k - 64) * H_ + u];
            }
        } else {
            int f = pos - 64;
            v = (k < 64) ? Wfre_s[k * F_ + f] : Wfre_m[(k - 64) * F_ + f];
        }
        g_Wcat[idx] = v;
    }

    // bcat [1280]
    for (int n = tid; n < NPRE; n += nth) {
        int chunk = n / 80, pos = n - chunk * 80;
        float v;
        if (pos < 64) {
            int gg = pos >> 4, u = chunk * 16 + (pos & 15);
            v = (gg == 0) ? bi[u] : (gg == 1) ? bste[u] : (gg == 2) ? bc[u] : bo[u];
        } else {
            v = bfre[pos - 64];
        }
        g_bcat[n] = v;
    }

    // Ucat [16][256][80]
    for (int idx = tid; idx < C_ * 256 * 80; idx += nth) {
        int chunk = idx / (256 * 80);
        int rem = idx - chunk * (256 * 80);
        int k = rem / 80, pos = rem - k * 80;
        float v;
        if (pos < 64) {
            int gg = pos >> 4, u = chunk * 16 + (pos & 15);
            const float* U = (gg == 0) ? Ui : (gg == 1) ? Uste : (gg == 2) ? Uc : Uo;
            v = U[k * H_ + u];
        } else {
            v = Ufre[k * F_ + (pos - 64)];
        }
        g_Ucat[idx] = v;
    }

    for (int i = tid; i < B_ * H_; i += nth) g_h[i] = 0.f;
    for (int i = tid; i < G_ * 32; i += nth) g_bar[i] = 0u;
}

// ---------------------------------------------------------------------------
// Precompute Xz = [signal|metmast] @ Wcat + bcat.  M=32768 (m=b*T+t), K=96.
// Fully coalesced A loads (m consecutive = t consecutive within a batch row).
// ---------------------------------------------------------------------------
__global__ __launch_bounds__(256) void gemm_pre(
    const float* __restrict__ signal, const float* __restrict__ metmast)
{
    __shared__ float2 As2[2][64][16];
    __shared__ __align__(16) float Bs[2][16][64];
    int m0 = blockIdx.x * 64, n0 = blockIdx.y * 64;
    int tid = threadIdx.x;
    int tx = tid & 15, ty4 = (tid >> 4) * 4;
    int nb = tx * 4;

    ull acc[4][2];
    #pragma unroll
    for (int i = 0; i < 4; i++) { acc[i][0] = 0ull; acc[i][1] = 0ull; }

    float asg[4], bsg[4];
    #pragma unroll
    for (int l = 0; l < 4; l++) {
        int idx = tid + l * 256;
        int ml = idx >> 4, kl = idx & 15;
        int m = m0 + ml;
        asg[l] = (kl < SIG_) ? signal[(size_t)m * SIG_ + kl]
                             : metmast[(size_t)m * MET_ + (kl - SIG_)];
    }
    #pragma unroll
    for (int l = 0; l < 4; l++) {
        int idx = tid + l * 256;
        int kl = idx >> 6, nl = idx & 63;
        bsg[l] = g_Wcat[kl * NPRE + n0 + nl];
    }
    #pragma unroll
    for (int l = 0; l < 4; l++) {
        int idx = tid + l * 256;
        int ml = idx >> 4, kl = idx & 15;
        As2[0][ml][kl] = make_float2(asg[l], asg[l]);
    }
    #pragma unroll
    for (int l = 0; l < 4; l++) {
        int idx = tid + l * 256;
        int kl = idx >> 6, nl = idx & 63;
        Bs[0][kl][nl] = bsg[l];
    }
    __syncthreads();

    #pragma unroll
    for (int c = 0; c < 6; c++) {
        int p = c & 1;
        if (c < 5) {
            int kk2 = (c + 1) * 16;
            #pragma unroll
            for (int l = 0; l < 4; l++) {
                int idx = tid + l * 256;
                int ml = idx >> 4, kl = idx & 15;
                int k = kk2 + kl;
                int m = m0 + ml;
                asg[l] = (k < SIG_) ? signal[(size_t)m * SIG_ + k]
                                    : metmast[(size_t)m * MET_ + (k - SIG_)];
            }
            #pragma unroll
            for (int l = 0; l < 4; l++) {
                int idx = tid + l * 256;
                int kl = idx >> 6, nl = idx & 63;
                bsg[l] = g_Wcat[(kk2 + kl) * NPRE + n0 + nl];
            }
        }
        #pragma unroll
        for (int k = 0; k < 16; k++) {
            ulonglong2 bb = *(const ulonglong2*)&Bs[p][k][nb];
            #pragma unroll
            for (int i = 0; i < 4; i++) {
                ull a = *(const ull*)&As2[p][ty4 + i][k];
                fma2(acc[i][0], a, bb.x);
                fma2(acc[i][1], a, bb.y);
            }
        }
        if (c < 5) {
            int q = p ^ 1;
            #pragma unroll
            for (int l = 0; l < 4; l++) {
                int idx = tid + l * 256;
                int ml = idx >> 4, kl = idx & 15;
                As2[q][ml][kl] = make_float2(asg[l], asg[l]);
            }
            #pragma unroll
            for (int l = 0; l < 4; l++) {
                int idx = tid + l * 256;
                int kl = idx >> 6, nl = idx & 63;
                Bs[q][kl][nl] = bsg[l];
            }
        }
        __syncthreads();
    }

    #pragma unroll
    for (int i = 0; i < 4; i++) {
        int m = m0 + ty4 + i, n = n0 + nb;
        float4 bias = *(const float4*)&g_bcat[n];
        float2 x01 = ull2f2(acc[i][0]), x23 = ull2f2(acc[i][1]);
        float4 o = make_float4(x01.x + bias.x, x01.y + bias.y,
                               x23.x + bias.z, x23.y + bias.w);
        *(float4*)&g_Xz[(size_t)m * NPRE + n] = o;
    }
}

// ---------------------------------------------------------------------------
// Persistent kernel: 128 blocks = 8 groups x 16 blocks.  Group owns 32 batch
// rows; block c owns units c*16..c*16+15.  U-slice + h live in smem; Z is
// block-local smem.  One group barrier per step (h exchange only).
// ---------------------------------------------------------------------------
extern __shared__ __align__(16) char smraw[];

__global__ void __launch_bounds__(512, 1) persist(
    const float* __restrict__ Ua, const float* __restrict__ ba,
    const float* __restrict__ Wp, const float* __restrict__ bp,
    const float* __restrict__ fcw, const float* __restrict__ fcb,
    float* __restrict__ out)
{
    float*  U_s   = (float*)(smraw);                    // [256][USTRIDE]   90112 B
    float2* h_dup = (float2*)(smraw + 90112);           // [32][HSTRIDE]    66048 B
    float*  Z_sm  = (float*)(smraw + 156160);           // [32][ZSTRIDE]    10752 B
    float2* red4  = (float2*)(smraw + 166912);          // [256][4]          8192 B
    float2* redf  = (float2*)(smraw + 175104);          // [256]             2048 B
    float*  fre_sm= (float*)(smraw + 177152);           // [32][16]          2048 B
    __shared__ float csh[16], ssh[16], ua_sh[16];

    int tid = threadIdx.x;
    int blk = blockIdx.x;
    int g = blk >> 4, c = blk & 15;
    int gb0 = g * 32;

    // update mapping: thread = (row, unit-local)
    int row_u = tid >> 4, ul = tid & 15;
    int b_u = gb0 + row_u;
    int u_glob = c * 16 + ul;
    // main GEMM mapping
    int cg = tid & 15, rg = (tid >> 4) & 15, kh = tid >> 8;
    // fre GEMM mapping
    int fcp = tid & 7, fr = (tid >> 3) & 31;

    // load U slice into smem (once)
    for (int i = tid; i < 256 * 80; i += 512) {
        int k = i / 80, p = i - k * 80;
        U_s[k * USTRIDE + p] = g_Ucat[(c * 256 + k) * 80 + p];
    }
    if (tid < 16) ua_sh[tid] = Ua[tid];
    float bah = ba[u_glob];

    float Sre[16], Sim[16];
    #pragma unroll
    for (int f = 0; f < 16; f++) { Sre[f] = 0.f; Sim[f] = 0.f; }
    __syncthreads();

    unsigned epoch = 0;
    unsigned* barp = &g_bar[g * 32];

    for (int t = 1; t <= T_; t++) {
        // ---- prefetch gate inputs for this step (coalesced, streaming) ----
        size_t xi = ((size_t)b_u * T_ + (t - 1)) * NPRE + c * 80 + ul;
        float pzi = __ldcs(&g_Xz[xi]);
        float pzs = __ldcs(&g_Xz[xi + 16]);
        float pzc = __ldcs(&g_Xz[xi + 32]);
        float pzo = __ldcs(&g_Xz[xi + 48]);
        float pzf = __ldcs(&g_Xz[xi + 64 - ul + ul]);  // fre col = base+64+f, f=ul
        pzf = __ldcs(&g_Xz[((size_t)b_u * T_ + (t - 1)) * NPRE + c * 80 + 64 + ul]);
        if (tid < 16) {
            int p = (t * tid) & 15;
            csh[tid] = cospif((float)p * 0.125f);
            ssh[tid] = sinpif((float)p * 0.125f);
        }

        if (t > 1) {
            // ---- main GEMM: Z[32 x 64 gate cols] = h @ U_s, k split in 2 ----
            ull a00 = 0, a01 = 0, a10 = 0, a11 = 0;
            {
                const float2* hp0 = h_dup + (rg * 2) * HSTRIDE + kh * 128;
                const float2* hp1 = hp0 + HSTRIDE;
                const float* up = U_s + (kh * 128) * USTRIDE + cg * 4;
                #pragma unroll 4
                for (int k = 0; k < 128; k++) {
                    ull h0 = *(const ull*)(hp0 + k);
                    ull h1 = *(const ull*)(hp1 + k);
                    ulonglong2 uu = *(const ulonglong2*)(up + k * USTRIDE);
                    fma2(a00, h0, uu.x); fma2(a01, h0, uu.y);
                    fma2(a10, h1, uu.x); fma2(a11, h1, uu.y);
                }
            }
            // ---- fre GEMM: Z[32 x 16 fre cols] ----
            ull af = 0;
            {
                const float2* hp = h_dup + fr * HSTRIDE + kh * 128;
                const float* up = U_s + (kh * 128) * USTRIDE + 64 + fcp * 2;
                #pragma unroll 4
                for (int k = 0; k < 128; k++) {
                    ull hh = *(const ull*)(hp + k);
                    ull uu = *(const ull*)(up + k * USTRIDE);
                    fma2(af, hh, uu);
                }
            }
            // ---- k-split reduction + write Z_sm ----
            int p = tid & 255;
            if (kh == 1) {
                red4[p * 4 + 0] = ull2f2(a00);
                red4[p * 4 + 1] = ull2f2(a01);
                red4[p * 4 + 2] = ull2f2(a10);
                red4[p * 4 + 3] = ull2f2(a11);
                redf[p] = ull2f2(af);
            }
            __syncthreads();
            if (kh == 0) {
                float2 m00 = ull2f2(a00), m01 = ull2f2(a01);
                float2 m10 = ull2f2(a10), m11 = ull2f2(a11);
                float2 q0 = red4[p * 4 + 0], q1 = red4[p * 4 + 1];
                float2 q2 = red4[p * 4 + 2], q3 = red4[p * 4 + 3];
                int r0 = rg * 2, col = cg * 4;
                *(float2*)&Z_sm[r0 * ZSTRIDE + col] =
                    make_float2(m00.x + q0.x, m00.y + q0.y);
                *(float2*)&Z_sm[r0 * ZSTRIDE + col + 2] =
                    make_float2(m01.x + q1.x, m01.y + q1.y);
                *(float2*)&Z_sm[(r0 + 1) * ZSTRIDE + col] =
                    make_float2(m10.x + q2.x, m10.y + q2.y);
                *(float2*)&Z_sm[(r0 + 1) * ZSTRIDE + col + 2] =
                    make_float2(m11.x + q3.x, m11.y + q3.y);
                float2 mf = ull2f2(af), qf = redf[p];
                *(float2*)&Z_sm[fr * ZSTRIDE + 64 + fcp * 2] =
                    make_float2(mf.x + qf.x, mf.y + qf.y);
            }
            __syncthreads();
        }

        // ---- fre gate ----
        {
            float zf = pzf;
            if (t > 1) zf += Z_sm[row_u * ZSTRIDE + 64 + ul];
            fre_sm[row_u * 16 + ul] = hsig(zf);
        }
        __syncthreads();

        // ---- gates + SFM state update ----
        float zi = pzi, zs = pzs, zc = pzc, zo = pzo;
        if (t > 1) {
            zi += Z_sm[row_u * ZSTRIDE + ul];
            zs += Z_sm[row_u * ZSTRIDE + 16 + ul];
            zc += Z_sm[row_u * ZSTRIDE + 32 + ul];
            zo += Z_sm[row_u * ZSTRIDE + 48 + ul];
        }
        float ig  = hsig(zi);
        float ste = hsig(zs);
        float og  = hsig(zo);
        float cgt = ig * tanhf(zc);

        float acc = 0.f;
        #pragma unroll
        for (int f = 0; f < 16; f++) {
            float ff = ste * fre_sm[row_u * 16 + f];
            float Sr = ff * Sre[f] + cgt * csh[f];
            float Si = ff * Sim[f] + cgt * ssh[f];
            Sre[f] = Sr; Sim[f] = Si;
            acc += (Sr * Sr + Si * Si) * ua_sh[f];
        }
        float hn = og * tanhf(acc + bah);
        g_h[b_u * H_ + u_glob] = hn;

        // ---- group barrier (h exchange) ----
        epoch += C_;
        __syncthreads();
        if (tid == 0) {
            __threadfence();
            atomicAdd(barp, 1u);
            unsigned v;
            do {
                asm volatile("ld.volatile.global.u32 %0, [%1];"
                             : "=r"(v) : "l"(barp));
            } while (v < epoch);
            __threadfence();
        }
        __syncthreads();

        // ---- reload group h into smem (duplicated) for next step ----
        if (t < T_) {
            for (int i = tid; i < 32 * 256; i += 512) {
                int r = i >> 8, k = i & 255;
                float v = __ldcg(&g_h[(gb0 + r) * H_ + k]);
                h_dup[r * HSTRIDE + k] = make_float2(v, v);
            }
            __syncthreads();
        }
    }

    // ---- final projection: block c==0 of each group handles its 32 rows ----
    if (c == 0) {
        int row = tid >> 4, j = tid & 15;
        float s = 0.f;
        #pragma unroll
        for (int l = 0; l < 16; l++)
            s += __ldcg(&g_h[(gb0 + row) * H_ + j * 16 + l]) * Wp[j * 16 + l];
        #pragma unroll
        for (int o = 8; o; o >>= 1) s += __shfl_xor_sync(0xffffffffu, s, o);
        if (j == 0) out[gb0 + row] = (s + bp[0]) * fcw[0] + fcb[0];
    }
}

// ---------------------------------------------------------------------------
#define SMEM_PERSIST 179200

extern "C" void kernel_launch(void* const* d_in, const int* in_sizes, int n_in,
                              void* d_out, int out_size)
{
    (void)in_sizes; (void)n_in; (void)out_size;
    const float* signal  = (const float*)d_in[0];
    const float* metmast = (const float*)d_in[1];
    const float* Wi_s    = (const float*)d_in[2];
    const float* Wste_s  = (const float*)d_in[3];
    const float* Wfre_s  = (const float*)d_in[4];
    const float* Wc_s    = (const float*)d_in[5];
    const float* Wo_s    = (const float*)d_in[6];
    const float* Wi_m    = (const float*)d_in[7];
    const float* Wste_m  = (const float*)d_in[8];
    const float* Wfre_m  = (const float*)d_in[9];
    const float* Wc_m    = (const float*)d_in[10];
    const float* Wo_m    = (const float*)d_in[11];
    const float* Ui      = (const float*)d_in[12];
    const float* bi      = (const float*)d_in[13];
    const float* Uste    = (const float*)d_in[14];
    const float* bste    = (const float*)d_in[15];
    const float* Ufre    = (const float*)d_in[16];
    const float* bfre    = (const float*)d_in[17];
    const float* Uc      = (const float*)d_in[18];
    const float* bc      = (const float*)d_in[19];
    const float* Uo      = (const float*)d_in[20];
    const float* bo      = (const float*)d_in[21];
    const float* Ua      = (const float*)d_in[22];
    const float* ba      = (const float*)d_in[23];
    const float* Wp      = (const float*)d_in[24];
    const float* bp      = (const float*)d_in[25];
    const float* fcw     = (const float*)d_in[26];
    const float* fcb     = (const float*)d_in[27];
    float* out = (float*)d_out;

    cudaFuncSetAttribute(persist,
                         cudaFuncAttributeMaxDynamicSharedMemorySize,
                         SMEM_PERSIST);

    setup_kernel<<<512, 256>>>(Wi_s, Wste_s, Wfre_s, Wc_s, Wo_s,
                               Wi_m, Wste_m, Wfre_m, Wc_m, Wo_m,
                               Ui, Uste, Ufre, Uc, Uo,
                               bi, bste, bfre, bc, bo);

    gemm_pre<<<dim3(B_ * T_ / 64, NPRE / 64), 256>>>(signal, metmast);

    persist<<<NBLK, 512, SMEM_PERSIST>>>(Ua, ba, Wp, bp, fcw, fcb, out);
}

// round 12
// speedup vs baseline: 1.1026x; 1.0313x over previous
#include <cuda_runtime.h>

#define B_   256
#define T_   128
#define SIG_ 64
#define MET_ 32
#define H_   256
#define F_   16
#define NPRE 1280      // pre-GEMM N: 16 chunks x 80 cols [i16|ste16|c16|o16|fre16]
#define C_   16        // blocks per group
#define G_   8         // groups
#define NBLK 128
#define ZSTRIDE 84

// persist smem layout (bytes)
#define U_OFF   0         // U_dup: [256 k][64 f2] row=512B            131072
#define UF_OFF  131072    // Ufre:  [256 k][16 f]  row=64B              16384
#define HP_OFF  147456    // h_pairs: [256 k][16 f2 +pad] row=144B      36864
#define RED_OFF 184320    // reduction scratch                          32768
#define Z_OFF   217088    // Z_sm: [32][84] float                       10752
#define FRE_OFF 227840    // fre_sm: [32][16] float                      2048
#define SMEM_PERSIST 229888

typedef unsigned long long ull;

// ---- persistent scratch (device globals; no allocation) ----
__device__ float  g_Wcat[96 * NPRE];
__device__ float  g_bcat[NPRE];
__device__ float2 g_Udup[C_ * 256 * 64];           // [chunk][k][64] dup pairs, permuted
__device__ float  g_Ufre[256 * F_];                // [k][f]
__device__ float  g_Xz[(size_t)B_ * T_ * NPRE];    // [b][t][1280]
__device__ float  g_h[B_ * H_];
__device__ unsigned g_bar[G_ * 32];                // per-group counters, 128B apart

__device__ __forceinline__ void fma2(ull& d, ull a, ull b) {
    asm("fma.rn.f32x2 %0, %1, %2, %0;" : "+l"(d) : "l"(a), "l"(b));
}
__device__ __forceinline__ void add2(ull& d, ull s) {
    asm("add.rn.f32x2 %0, %0, %1;" : "+l"(d) : "l"(s));
}
__device__ __forceinline__ ull dupf(float x) {
    ull r; asm("mov.b64 %0, {%1,%1};" : "=l"(r) : "f"(x)); return r;
}
__device__ __forceinline__ float2 ull2f2(ull v) {
    float2 r; asm("mov.b64 {%0,%1}, %2;" : "=f"(r.x), "=f"(r.y) : "l"(v)); return r;
}
__device__ __forceinline__ float hsig(float x) {
    return __saturatef(x * (1.0f / 6.0f) + 0.5f);
}

// ---------------------------------------------------------------------------
// Setup: permuted weights/bias, duplicated U, zero h + barrier counters.
// Chunk-local column pos 0..79: pos<64 -> gate g=pos>>4 (i,ste,c,o),
// unit u = chunk*16 + (pos&15); pos>=64 -> fre f = pos-64.
// U_dup row layout (f2 index j 0..63): half=j>>5, cg=(j&31)>>1,
// pos = 4*cg + (j&1) + 2*half; value = dup(U[k][pos-mapped unit]).
// ---------------------------------------------------------------------------
__global__ void setup_kernel(
    const float* __restrict__ Wi_s,  const float* __restrict__ Wste_s,
    const float* __restrict__ Wfre_s,const float* __restrict__ Wc_s,
    const float* __restrict__ Wo_s,
    const float* __restrict__ Wi_m,  const float* __restrict__ Wste_m,
    const float* __restrict__ Wfre_m,const float* __restrict__ Wc_m,
    const float* __restrict__ Wo_m,
    const float* __restrict__ Ui,    const float* __restrict__ Uste,
    const float* __restrict__ Ufre,  const float* __restrict__ Uc,
    const float* __restrict__ Uo,
    const float* __restrict__ bi,    const float* __restrict__ bste,
    const float* __restrict__ bfre,  const float* __restrict__ bc,
    const float* __restrict__ bo)
{
    int tid = blockIdx.x * blockDim.x + threadIdx.x;
    int nth = gridDim.x * blockDim.x;

    for (int idx = tid; idx < 96 * NPRE; idx += nth) {
        int k = idx / NPRE, n = idx - k * NPRE;
        int chunk = n / 80, pos = n - chunk * 80;
        float v;
        if (pos < 64) {
            int gg = pos >> 4, u = chunk * 16 + (pos & 15);
            if (k < 64) {
                const float* W = (gg == 0) ? Wi_s : (gg == 1) ? Wste_s : (gg == 2) ? Wc_s : Wo_s;
                v = W[k * H_ + u];
            } else {
                const float* W = (gg == 0) ? Wi_m : (gg == 1) ? Wste_m : (gg == 2) ? Wc_m : Wo_m;
                v = W[(k - 64) * H_ + u];
            }
        } else {
            int f = pos - 64;
            v = (k < 64) ? Wfre_s[k * F_ + f] : Wfre_m[(k - 64) * F_ + f];
        }
        g_Wcat[idx] = v;
    }

    for (int n = tid; n < NPRE; n += nth) {
        int chunk = n / 80, pos = n - chunk * 80;
        float v;
        if (pos < 64) {
            int gg = pos >> 4, u = chunk * 16 + (pos & 15);
            v = (gg == 0) ? bi[u] : (gg == 1) ? bste[u] : (gg == 2) ? bc[u] : bo[u];
        } else {
            v = bfre[pos - 64];
        }
        g_bcat[n] = v;
    }

    for (int idx = tid; idx < C_ * 256 * 64; idx += nth) {
        int chunk = idx / (256 * 64);
        int rem = idx - chunk * (256 * 64);
        int k = rem >> 6, j = rem & 63;
        int half = j >> 5, cg = (j & 31) >> 1;
        int pos = 4 * cg + (j & 1) + 2 * half;
        int gg = pos >> 4, u = chunk * 16 + (pos & 15);
        const float* U = (gg == 0) ? Ui : (gg == 1) ? Uste : (gg == 2) ? Uc : Uo;
        float v = U[k * H_ + u];
        g_Udup[idx] = make_float2(v, v);
    }

    for (int idx = tid; idx < 256 * F_; idx += nth) g_Ufre[idx] = Ufre[idx];

    for (int i = tid; i < B_ * H_; i += nth) g_h[i] = 0.f;
    for (int i = tid; i < G_ * 32; i += nth) g_bar[i] = 0u;
}

// ---------------------------------------------------------------------------
// Precompute Xz = [signal|metmast] @ Wcat + bcat.  M=32768 (m=b*T+t), K=96.
// ---------------------------------------------------------------------------
__global__ __launch_bounds__(256) void gemm_pre(
    const float* __restrict__ signal, const float* __restrict__ metmast)
{
    __shared__ float2 As2[2][64][16];
    __shared__ __align__(16) float Bs[2][16][64];
    int m0 = blockIdx.x * 64, n0 = blockIdx.y * 64;
    int tid = threadIdx.x;
    int tx = tid & 15, ty4 = (tid >> 4) * 4;
    int nb = tx * 4;

    ull acc[4][2];
    #pragma unroll
    for (int i = 0; i < 4; i++) { acc[i][0] = 0ull; acc[i][1] = 0ull; }

    float asg[4], bsg[4];
    #pragma unroll
    for (int l = 0; l < 4; l++) {
        int idx = tid + l * 256;
        int ml = idx >> 4, kl = idx & 15;
        int m = m0 + ml;
        asg[l] = (kl < SIG_) ? signal[(size_t)m * SIG_ + kl]
                             : metmast[(size_t)m * MET_ + (kl - SIG_)];
    }
    #pragma unroll
    for (int l = 0; l < 4; l++) {
        int idx = tid + l * 256;
        int kl = idx >> 6, nl = idx & 63;
        bsg[l] = g_Wcat[kl * NPRE + n0 + nl];
    }
    #pragma unroll
    for (int l = 0; l < 4; l++) {
        int idx = tid + l * 256;
        int ml = idx >> 4, kl = idx & 15;
        As2[0][ml][kl] = make_float2(asg[l], asg[l]);
    }
    #pragma unroll
    for (int l = 0; l < 4; l++) {
        int idx = tid + l * 256;
        int kl = idx >> 6, nl = idx & 63;
        Bs[0][kl][nl] = bsg[l];
    }
    __syncthreads();

    #pragma unroll
    for (int cc = 0; cc < 6; cc++) {
        int p = cc & 1;
        if (cc < 5) {
            int kk2 = (cc + 1) * 16;
            #pragma unroll
            for (int l = 0; l < 4; l++) {
                int idx = tid + l * 256;
                int ml = idx >> 4, kl = idx & 15;
                int k = kk2 + kl;
                int m = m0 + ml;
                asg[l] = (k < SIG_) ? signal[(size_t)m * SIG_ + k]
                                    : metmast[(size_t)m * MET_ + (k - SIG_)];
            }
            #pragma unroll
            for (int l = 0; l < 4; l++) {
                int idx = tid + l * 256;
                int kl = idx >> 6, nl = idx & 63;
                bsg[l] = g_Wcat[(kk2 + kl) * NPRE + n0 + nl];
            }
        }
        #pragma unroll
        for (int k = 0; k < 16; k++) {
            ulonglong2 bb = *(const ulonglong2*)&Bs[p][k][nb];
            #pragma unroll
            for (int i = 0; i < 4; i++) {
                ull a = *(const ull*)&As2[p][ty4 + i][k];
                fma2(acc[i][0], a, bb.x);
                fma2(acc[i][1], a, bb.y);
            }
        }
        if (cc < 5) {
            int q = p ^ 1;
            #pragma unroll
            for (int l = 0; l < 4; l++) {
                int idx = tid + l * 256;
                int ml = idx >> 4, kl = idx & 15;
                As2[q][ml][kl] = make_float2(asg[l], asg[l]);
            }
            #pragma unroll
            for (int l = 0; l < 4; l++) {
                int idx = tid + l * 256;
                int kl = idx >> 6, nl = idx & 63;
                Bs[q][kl][nl] = bsg[l];
            }
        }
        __syncthreads();
    }

    #pragma unroll
    for (int i = 0; i < 4; i++) {
        int m = m0 + ty4 + i, n = n0 + nb;
        float4 bias = *(const float4*)&g_bcat[n];
        float2 x01 = ull2f2(acc[i][0]), x23 = ull2f2(acc[i][1]);
        float4 o = make_float4(x01.x + bias.x, x01.y + bias.y,
                               x23.x + bias.z, x23.y + bias.w);
        *(float4*)&g_Xz[(size_t)m * NPRE + n] = o;
    }
}

// ---------------------------------------------------------------------------
// Persistent kernel: 128 blocks = 8 groups x 16 blocks.  Group owns 32 batch
// rows; block c owns units c*16..c*16+15.  FFMA2-bound GEMM: f32x2 over
// M-pairs (h_pairs k-major, no dup), U duplicated+permuted in smem.
// Thread tile 4 Mpairs x 4 cols, k-split 8 (kq = tid>>6), tree reduction.
// ---------------------------------------------------------------------------
extern __shared__ __align__(16) char smraw[];

__global__ void __launch_bounds__(512, 1) persist(
    const float* __restrict__ Ua, const float* __restrict__ ba,
    const float* __restrict__ Wp, const float* __restrict__ bp,
    const float* __restrict__ fcw, const float* __restrict__ fcb,
    float* __restrict__ out)
{
    float* Z_sm   = (float*)(smraw + Z_OFF);
    float* fre_sm = (float*)(smraw + FRE_OFF);
    __shared__ float csh[16], ssh[16], ua_sh[16];

    int tid = threadIdx.x;
    int blk = blockIdx.x;
    int g = blk >> 4, c = blk & 15;
    int gb0 = g * 32;

    // update mapping
    int row_u = tid >> 4, ul = tid & 15;
    int b_u = gb0 + row_u;
    int u_glob = c * 16 + ul;
    // main GEMM mapping: kq = k-eighth, mg = Mpair-group(4), cg = col-group(4)
    int cg = tid & 15, mg = (tid >> 4) & 3, kq = tid >> 6;
    // fre GEMM mapping
    int cgf = tid & 3, mgf = (tid >> 2) & 15;

    // ---- one-time: load U slice (dup+permuted) and Ufre into smem ----
    for (int i = tid; i < 256 * 64; i += 512) {
        int k = i >> 6, j = i & 63;
        *(float2*)(smraw + U_OFF + k * 512 + j * 8) = g_Udup[(c * 256 + k) * 64 + j];
    }
    for (int i = tid; i < 256 * F_; i += 512)
        ((float*)(smraw + UF_OFF))[i] = g_Ufre[i];
    if (tid < 16) ua_sh[tid] = Ua[tid];
    float bah = ba[u_glob];

    float Sre[16], Sim[16];
    #pragma unroll
    for (int f = 0; f < 16; f++) { Sre[f] = 0.f; Sim[f] = 0.f; }
    __syncthreads();

    unsigned epoch = 0;
    unsigned* barp = &g_bar[g * 32];

    for (int t = 1; t <= T_; t++) {
        // ---- prefetch gate inputs (depend only on t) ----
        size_t xi = ((size_t)b_u * T_ + (t - 1)) * NPRE + c * 80 + ul;
        float pzi = __ldcs(&g_Xz[xi]);
        float pzs = __ldcs(&g_Xz[xi + 16]);
        float pzc = __ldcs(&g_Xz[xi + 32]);
        float pzo = __ldcs(&g_Xz[xi + 48]);
        float pzf = __ldcs(&g_Xz[xi + 64]);
        if (tid < 16) {
            int p = (t * tid) & 15;
            csh[tid] = cospif((float)p * 0.125f);
            ssh[tid] = sinpif((float)p * 0.125f);
        }

        if (t > 1) {
            // ---- main GEMM: acc[i][j] = (Z[2mp][col], Z[2mp+1][col]) ----
            ull acc[4][4];
            #pragma unroll
            for (int i = 0; i < 4; i++)
                #pragma unroll
                for (int j = 0; j < 4; j++) acc[i][j] = 0ull;
            {
                const char* hb = smraw + HP_OFF + (kq * 32) * 144 + mg * 32;
                const char* ub = smraw + U_OFF + (kq * 32) * 512 + cg * 16;
                #pragma unroll 4
                for (int kk = 0; kk < 32; kk++) {
                    ulonglong2 a01 = *(const ulonglong2*)(hb);
                    ulonglong2 b01 = *(const ulonglong2*)(ub);
                    ulonglong2 b23 = *(const ulonglong2*)(ub + 256);
                    fma2(acc[0][0], a01.x, b01.x); fma2(acc[0][1], a01.x, b01.y);
                    fma2(acc[0][2], a01.x, b23.x); fma2(acc[0][3], a01.x, b23.y);
                    fma2(acc[1][0], a01.y, b01.x); fma2(acc[1][1], a01.y, b01.y);
                    fma2(acc[1][2], a01.y, b23.x); fma2(acc[1][3], a01.y, b23.y);
                    ulonglong2 a23 = *(const ulonglong2*)(hb + 16);
                    fma2(acc[2][0], a23.x, b01.x); fma2(acc[2][1], a23.x, b01.y);
                    fma2(acc[2][2], a23.x, b23.x); fma2(acc[2][3], a23.x, b23.y);
                    fma2(acc[3][0], a23.y, b01.x); fma2(acc[3][1], a23.y, b01.y);
                    fma2(acc[3][2], a23.y, b23.x); fma2(acc[3][3], a23.y, b23.y);
                    hb += 144; ub += 512;
                }
            }
            // ---- fre GEMM: 1 Mpair x 4 cols per thread ----
            ull facc[4] = {0ull, 0ull, 0ull, 0ull};
            {
                const char* hb = smraw + HP_OFF + (kq * 32) * 144 + mgf * 8;
                const char* ub = smraw + UF_OFF + (kq * 32) * 64 + cgf * 16;
                #pragma unroll 4
                for (int kk = 0; kk < 32; kk++) {
                    ull a = *(const ull*)(hb);
                    float4 u4 = *(const float4*)(ub);
                    fma2(facc[0], a, dupf(u4.x));
                    fma2(facc[1], a, dupf(u4.y));
                    fma2(facc[2], a, dupf(u4.z));
                    fma2(facc[3], a, dupf(u4.w));
                    hb += 144; ub += 64;
                }
            }
            // ---- tree reduction over kq (8 -> 1) ----
            ull* red = (ull*)(smraw + RED_OFF);
            ull* fred = (ull*)(smraw + RED_OFF + 8192);
            if (tid >= 256) {
                ull* d = red + (tid - 256) * 16;
                #pragma unroll
                for (int i = 0; i < 4; i++)
                    #pragma unroll
                    for (int j = 0; j < 4; j++) d[i * 4 + j] = acc[i][j];
            }
            __syncthreads();
            if (tid < 256) {
                const ull* s = red + tid * 16;
                #pragma unroll
                for (int i = 0; i < 4; i++)
                    #pragma unroll
                    for (int j = 0; j < 4; j++) add2(acc[i][j], s[i * 4 + j]);
            }
            __syncthreads();
            if (tid >= 128 && tid < 256) {
                ull* d = red + (tid - 128) * 16;
                #pragma unroll
                for (int i = 0; i < 4; i++)
                    #pragma unroll
                    for (int j = 0; j < 4; j++) d[i * 4 + j] = acc[i][j];
            }
            __syncthreads();
            if (tid < 128) {
                const ull* s = red + tid * 16;
                #pragma unroll
                for (int i = 0; i < 4; i++)
                    #pragma unroll
                    for (int j = 0; j < 4; j++) add2(acc[i][j], s[i * 4 + j]);
            }
            __syncthreads();
            if (tid >= 64 && tid < 128) {
                ull* d = red + (tid - 64) * 16;
                #pragma unroll
                for (int i = 0; i < 4; i++)
                    #pragma unroll
                    for (int j = 0; j < 4; j++) d[i * 4 + j] = acc[i][j];
            }
            // fre partial store (all threads): fred[a][520-stride]
            #pragma unroll
            for (int a = 0; a < 4; a++) fred[a * 520 + tid] = facc[a];
            __syncthreads();
            if (tid < 64) {
                const ull* s = red + tid * 16;
                #pragma unroll
                for (int i = 0; i < 4; i++)
                    #pragma unroll
                    for (int j = 0; j < 4; j++) {
                        add2(acc[i][j], s[i * 4 + j]);
                        float2 v = ull2f2(acc[i][j]);
                        int mp = mg * 4 + i;
                        int col = cg * 4 + j;
                        Z_sm[(2 * mp) * ZSTRIDE + col] = v.x;
                        Z_sm[(2 * mp + 1) * ZSTRIDE + col] = v.y;
                    }
            }
            if (tid >= 256) {
                int q = tid - 256;
                int mq = q >> 4, cq = (q >> 2) & 3, j = q & 3;
                int w = mq * 4 + cq;
                ull s = 0ull;
                #pragma unroll
                for (int p = 0; p < 8; p++) add2(s, fred[j * 520 + p * 64 + w]);
                float2 v = ull2f2(s);
                int col = 64 + cq * 4 + j;
                Z_sm[(2 * mq) * ZSTRIDE + col] = v.x;
                Z_sm[(2 * mq + 1) * ZSTRIDE + col] = v.y;
            }
            __syncthreads();
        }

        // ---- fre gate ----
        {
            float zf = pzf;
            if (t > 1) zf += Z_sm[row_u * ZSTRIDE + 64 + ul];
            fre_sm[row_u * 16 + ul] = hsig(zf);
        }
        __syncthreads();

        // ---- gates + SFM state update ----
        float zi = pzi, zs = pzs, zc = pzc, zo = pzo;
        if (t > 1) {
            zi += Z_sm[row_u * ZSTRIDE + ul];
            zs += Z_sm[row_u * ZSTRIDE + 16 + ul];
            zc += Z_sm[row_u * ZSTRIDE + 32 + ul];
            zo += Z_sm[row_u * ZSTRIDE + 48 + ul];
        }
        float ig  = hsig(zi);
        float ste = hsig(zs);
        float og  = hsig(zo);
        float cgt = ig * tanhf(zc);

        float acc_a = 0.f;
        #pragma unroll
        for (int f = 0; f < 16; f++) {
            float ff = ste * fre_sm[row_u * 16 + f];
            float Sr = ff * Sre[f] + cgt * csh[f];
            float Si = ff * Sim[f] + cgt * ssh[f];
            Sre[f] = Sr; Sim[f] = Si;
            acc_a += (Sr * Sr + Si * Si) * ua_sh[f];
        }
        float hn = og * tanhf(acc_a + bah);
        g_h[b_u * H_ + u_glob] = hn;

        // ---- group barrier (h exchange) ----
        epoch += C_;
        __syncthreads();
        if (tid == 0) {
            __threadfence();
            atomicAdd(barp, 1u);
            unsigned v;
            do {
                asm volatile("ld.volatile.global.u32 %0, [%1];"
                             : "=r"(v) : "l"(barp));
            } while (v < epoch);
            __threadfence();
        }
        __syncthreads();

        // ---- rebuild h_pairs (k-major M-pairs) for next step ----
        if (t < T_) {
            for (int i = tid; i < 4096; i += 512) {
                int mp = i >> 8, k = i & 255;
                float v0 = __ldcg(&g_h[(gb0 + 2 * mp) * H_ + k]);
                float v1 = __ldcg(&g_h[(gb0 + 2 * mp + 1) * H_ + k]);
                *(float2*)(smraw + HP_OFF + k * 144 + mp * 8) = make_float2(v0, v1);
            }
            __syncthreads();
        }
    }

    // ---- final projection: block c==0 of each group handles its 32 rows ----
    if (c == 0) {
        int row = tid >> 4, j = tid & 15;
        float s = 0.f;
        #pragma unroll
        for (int l = 0; l < 16; l++)
            s += __ldcg(&g_h[(gb0 + row) * H_ + j * 16 + l]) * Wp[j * 16 + l];
        #pragma unroll
        for (int o = 8; o; o >>= 1) s += __shfl_xor_sync(0xffffffffu, s, o);
        if (j == 0) out[gb0 + row] = (s + bp[0]) * fcw[0] + fcb[0];
    }
}

// ---------------------------------------------------------------------------
extern "C" void kernel_launch(void* const* d_in, const int* in_sizes, int n_in,
                              void* d_out, int out_size)
{
    (void)in_sizes; (void)n_in; (void)out_size;
    const float* signal  = (const float*)d_in[0];
    const float* metmast = (const float*)d_in[1];
    const float* Wi_s    = (const float*)d_in[2];
    const float* Wste_s  = (const float*)d_in[3];
    const float* Wfre_s  = (const float*)d_in[4];
    const float* Wc_s    = (const float*)d_in[5];
    const float* Wo_s    = (const float*)d_in[6];
    const float* Wi_m    = (const float*)d_in[7];
    const float* Wste_m  = (const float*)d_in[8];
    const float* Wfre_m  = (const float*)d_in[9];
    const float* Wc_m    = (const float*)d_in[10];
    const float* Wo_m    = (const float*)d_in[11];
    const float* Ui      = (const float*)d_in[12];
    const float* bi      = (const float*)d_in[13];
    const float* Uste    = (const float*)d_in[14];
    const float* bste    = (const float*)d_in[15];
    const float* Ufre    = (const float*)d_in[16];
    const float* bfre    = (const float*)d_in[17];
    const float* Uc      = (const float*)d_in[18];
    const float* bc      = (const float*)d_in[19];
    const float* Uo      = (const float*)d_in[20];
    const float* bo      = (const float*)d_in[21];
    const float* Ua      = (const float*)d_in[22];
    const float* ba      = (const float*)d_in[23];
    const float* Wp      = (const float*)d_in[24];
    const float* bp      = (const float*)d_in[25];
    const float* fcw     = (const float*)d_in[26];
    const float* fcb     = (const float*)d_in[27];
    float* out = (float*)d_out;

    cudaFuncSetAttribute(persist,
                         cudaFuncAttributeMaxDynamicSharedMemorySize,
                         SMEM_PERSIST);

    setup_kernel<<<512, 256>>>(Wi_s, Wste_s, Wfre_s, Wc_s, Wo_s,
                               Wi_m, Wste_m, Wfre_m, Wc_m, Wo_m,
                               Ui, Uste, Ufre, Uc, Uo,
                               bi, bste, bfre, bc, bo);

    gemm_pre<<<dim3(B_ * T_ / 64, NPRE / 64), 256>>>(signal, metmast);

    persist<<<NBLK, 512, SMEM_PERSIST>>>(Ua, ba, Wp, bp, fcw, fcb, out);
}